// round 4
// baseline (speedup 1.0000x reference)
#include <cuda_runtime.h>
#include <cuda_fp16.h>
#include <math.h>

#define DIMS 256
#define NROWS 4096

// Global scratch (no device allocation allowed).
__device__ float  g_acc[2];
__device__ __half g_Xh[NROWS * DIMS];   // 2 MB fp16 copy of Xemb

__global__ void zero_acc_kernel() {
    if (threadIdx.x < 2) g_acc[threadIdx.x] = 0.0f;
}

// Convert Xemb (fp32) -> g_Xh (fp16). 1M floats, 4 per thread.
__global__ void __launch_bounds__(256)
convert_kernel(const float* __restrict__ X) {
    int idx = blockIdx.x * blockDim.x + threadIdx.x;   // one float4 per thread
    float4 v = ((const float4*)X)[idx];
    __half2* out = (__half2*)g_Xh;
    out[2 * idx]     = __floats2half2_rn(v.x, v.y);
    out[2 * idx + 1] = __floats2half2_rn(v.z, v.w);
}

__device__ __forceinline__ float softplus_stable(float z) {
    return (z > 0.0f) ? (z + log1pf(expf(-z))) : log1pf(expf(z));
}

// Warp computes squared distance for pair (i, j) from the fp16 table.
// Row = 256 halves = 512 B = 32 lanes x 16 B.
__device__ __forceinline__ float pair_sqdist_w(int i, int j, int lane) {
    const float4* ri = (const float4*)(g_Xh + (size_t)i * DIMS);
    const float4* rj = (const float4*)(g_Xh + (size_t)j * DIMS);
    float4 a = ri[lane];
    float4 c = rj[lane];

    const __half2* ha = (const __half2*)&a;
    const __half2* hc = (const __half2*)&c;

    float s = 0.0f;
    #pragma unroll
    for (int k = 0; k < 4; ++k) {
        float2 fa = __half22float2(ha[k]);
        float2 fc = __half22float2(hc[k]);
        float d0 = fa.x - fc.x;
        float d1 = fa.y - fc.y;
        s = fmaf(d0, d0, s);
        s = fmaf(d1, d1, s);
    }
    #pragma unroll
    for (int off = 16; off > 0; off >>= 1)
        s += __shfl_xor_sync(0xFFFFFFFFu, s, off);
    return s;
}

// Each warp takes one contiguous chunk of pos pairs (L1 reuse: cluster rows)
// AND one contiguous chunk of neg pairs (balances L2-bound work).
__global__ void __launch_bounds__(256)
pair_loss_kernel(const float* __restrict__ bias,
                 const int*   __restrict__ pos_idx,
                 const int*   __restrict__ neg_idx,
                 int P)
{
    const int lane    = threadIdx.x & 31;
    const int warp_id = (blockIdx.x * blockDim.x + threadIdx.x) >> 5;
    const int nwarps  = (gridDim.x * blockDim.x) >> 5;

    const int chunk = (P + nwarps - 1) / nwarps;
    int p0 = warp_id * chunk;
    int p1 = p0 + chunk; if (p1 > P) p1 = P;

    const float b = bias[0];

    float acc_pos = 0.0f;
    for (int p = p0; p < p1; ++p) {
        int i = pos_idx[2 * p];
        int j = pos_idx[2 * p + 1];
        float s = pair_sqdist_w(i, j, lane);
        if (lane == 0) acc_pos += softplus_stable(s - b);   // softplus(-(b-d)) = softplus(d-b)
    }

    float acc_neg = 0.0f;
    for (int p = p0; p < p1; ++p) {
        int i = neg_idx[2 * p];
        int j = neg_idx[2 * p + 1];
        float s = pair_sqdist_w(i, j, lane);
        if (lane == 0) acc_neg += softplus_stable(b - s);
    }

    if (lane == 0) {
        if (acc_pos != 0.0f) atomicAdd(&g_acc[0], acc_pos);
        if (acc_neg != 0.0f) atomicAdd(&g_acc[1], acc_neg);
    }
}

__global__ void finalize_kernel(float* __restrict__ out, float inv_P) {
    if (threadIdx.x < 2) out[threadIdx.x] = g_acc[threadIdx.x] * inv_P;
}

extern "C" void kernel_launch(void* const* d_in, const int* in_sizes, int n_in,
                              void* d_out, int out_size)
{
    const float* X       = (const float*)d_in[0];   // [4096, 256] fp32
    const float* bias    = (const float*)d_in[1];   // [1]
    const int*   pos_idx = (const int*)d_in[2];     // [P, 2]
    const int*   neg_idx = (const int*)d_in[3];     // [P, 2]
    float*       out     = (float*)d_out;           // [2]

    const int P = in_sizes[2] / 2;

    zero_acc_kernel<<<1, 32>>>();

    // 4096*256 floats / 4 per thread / 256 threads = 1024 blocks
    convert_kernel<<<(NROWS * DIMS / 4) / 256, 256>>>(X);

    const int threads = 256;
    const int blocks  = 148 * 8;
    pair_loss_kernel<<<blocks, threads>>>(bias, pos_idx, neg_idx, P);

    finalize_kernel<<<1, 32>>>(out, 1.0f / (float)P);
}

// round 5
// speedup vs baseline: 1.9389x; 1.9389x over previous
#include <cuda_runtime.h>
#include <cuda_fp16.h>
#include <math.h>

#define DIM 256
#define NROWS 4096

// ---- static device scratch (no allocations allowed) ----
__device__ float        g_acc[2];
__device__ unsigned int g_done;
__device__ __half       g_Xh[NROWS * DIM];                    // 2 MB fp16 table
__device__ float        g_norm[NROWS];                        // row squared norms
__device__ float        g_G[(size_t)NROWS * NROWS];           // 64 MB Gram (lower-tri blocks valid)

// ============================================================================
// Prep: fp32 -> fp16 convert, row norms (from the fp16 values, for consistency
// with the Gram MMA), zero accumulators. One warp per row.
// grid = 512 blocks x 256 threads (8 warps) -> 4096 rows.
// ============================================================================
__global__ void __launch_bounds__(256)
prep_kernel(const float* __restrict__ X)
{
    const int warp = threadIdx.x >> 5;
    const int lane = threadIdx.x & 31;
    const int row  = blockIdx.x * 8 + warp;

    const float4* src = (const float4*)(X + (size_t)row * DIM);
    float4 v0 = src[lane * 2];
    float4 v1 = src[lane * 2 + 1];

    __half2 h0 = __floats2half2_rn(v0.x, v0.y);
    __half2 h1 = __floats2half2_rn(v0.z, v0.w);
    __half2 h2 = __floats2half2_rn(v1.x, v1.y);
    __half2 h3 = __floats2half2_rn(v1.z, v1.w);

    uint4 packed;
    packed.x = *(unsigned int*)&h0;
    packed.y = *(unsigned int*)&h1;
    packed.z = *(unsigned int*)&h2;
    packed.w = *(unsigned int*)&h3;
    ((uint4*)(g_Xh + (size_t)row * DIM))[lane] = packed;

    // norm from the quantized values
    float2 f0 = __half22float2(h0), f1 = __half22float2(h1);
    float2 f2 = __half22float2(h2), f3 = __half22float2(h3);
    float s = f0.x * f0.x;
    s = fmaf(f0.y, f0.y, s);
    s = fmaf(f1.x, f1.x, s); s = fmaf(f1.y, f1.y, s);
    s = fmaf(f2.x, f2.x, s); s = fmaf(f2.y, f2.y, s);
    s = fmaf(f3.x, f3.x, s); s = fmaf(f3.y, f3.y, s);
    #pragma unroll
    for (int off = 16; off > 0; off >>= 1)
        s += __shfl_xor_sync(0xFFFFFFFFu, s, off);
    if (lane == 0) g_norm[row] = s;

    if (blockIdx.x == 0 && threadIdx.x < 3) {
        if (threadIdx.x < 2) g_acc[threadIdx.x] = 0.0f;
        else                 g_done = 0u;
    }
}

// ============================================================================
// Gram GEMM: G = Xh * Xh^T, fp16 in / fp32 out via mma.sync.m16n8k16.
// Only lower-triangle blocks (bm >= bn); pair lookup uses (max,min).
// Block tile 128x128, 8 warps of 64x32, K chunked by 64 in padded SMEM.
// ============================================================================
__device__ __forceinline__ void mma16816(float c[4],
                                         const unsigned a[4],
                                         const unsigned b[2])
{
    asm volatile(
        "mma.sync.aligned.m16n8k16.row.col.f32.f16.f16.f32 "
        "{%0,%1,%2,%3}, {%4,%5,%6,%7}, {%8,%9}, {%0,%1,%2,%3};\n"
        : "+f"(c[0]), "+f"(c[1]), "+f"(c[2]), "+f"(c[3])
        : "r"(a[0]), "r"(a[1]), "r"(a[2]), "r"(a[3]),
          "r"(b[0]), "r"(b[1]));
}

__global__ void __launch_bounds__(256, 2)
gram_kernel()
{
    const int bn = blockIdx.x;
    const int bm = blockIdx.y;
    if (bm < bn) return;   // symmetric: compute lower-triangle blocks only

    __shared__ __half As[128][72];   // +8 halves pad -> conflict-free frag loads
    __shared__ __half Bs[128][72];

    const int tid  = threadIdx.x;
    const int warp = tid >> 5;
    const int lane = tid & 31;
    const int wm   = warp >> 2;      // 0..1  (64-row slabs)
    const int wn   = warp & 3;       // 0..3  (32-col slabs)
    const int tg   = lane >> 2;      // 0..7
    const int tq   = lane & 3;       // 0..3

    float acc[4][4][4];
    #pragma unroll
    for (int mi = 0; mi < 4; ++mi)
        #pragma unroll
        for (int ni = 0; ni < 4; ++ni)
            #pragma unroll
            for (int k = 0; k < 4; ++k) acc[mi][ni][k] = 0.0f;

    const int lr = tid >> 3;          // 0..31
    const int lc = (tid & 7) * 8;     // 0,8,...,56 halves

    for (int kc = 0; kc < 4; ++kc) {
        const int kbase = kc * 64;
        #pragma unroll
        for (int rr = 0; rr < 4; ++rr) {
            const int row = rr * 32 + lr;
            uint4 va = *(const uint4*)(g_Xh + (size_t)(bm * 128 + row) * DIM + kbase + lc);
            *(uint4*)(&As[row][lc]) = va;
            uint4 vb = *(const uint4*)(g_Xh + (size_t)(bn * 128 + row) * DIM + kbase + lc);
            *(uint4*)(&Bs[row][lc]) = vb;
        }
        __syncthreads();

        #pragma unroll
        for (int ks = 0; ks < 4; ++ks) {
            const int kk = ks * 16;
            unsigned a[4][4], b[4][2];
            #pragma unroll
            for (int mi = 0; mi < 4; ++mi) {
                const int r0 = wm * 64 + mi * 16 + tg;
                a[mi][0] = *(const unsigned*)(&As[r0][kk + tq * 2]);
                a[mi][1] = *(const unsigned*)(&As[r0 + 8][kk + tq * 2]);
                a[mi][2] = *(const unsigned*)(&As[r0][kk + tq * 2 + 8]);
                a[mi][3] = *(const unsigned*)(&As[r0 + 8][kk + tq * 2 + 8]);
            }
            #pragma unroll
            for (int ni = 0; ni < 4; ++ni) {
                const int j0 = wn * 32 + ni * 8 + tg;
                b[ni][0] = *(const unsigned*)(&Bs[j0][kk + tq * 2]);
                b[ni][1] = *(const unsigned*)(&Bs[j0][kk + tq * 2 + 8]);
            }
            #pragma unroll
            for (int mi = 0; mi < 4; ++mi)
                #pragma unroll
                for (int ni = 0; ni < 4; ++ni)
                    mma16816(acc[mi][ni], a[mi], b[ni]);
        }
        __syncthreads();
    }

    // store D fragments (float2 per 8B pair, coalesced-ish; G stays in L2)
    #pragma unroll
    for (int mi = 0; mi < 4; ++mi) {
        const int r0 = bm * 128 + wm * 64 + mi * 16 + tg;
        #pragma unroll
        for (int ni = 0; ni < 4; ++ni) {
            const int c0 = bn * 128 + wn * 32 + ni * 8 + tq * 2;
            *(float2*)(&g_G[(size_t)r0 * NROWS + c0]) =
                make_float2(acc[mi][ni][0], acc[mi][ni][1]);
            *(float2*)(&g_G[(size_t)(r0 + 8) * NROWS + c0]) =
                make_float2(acc[mi][ni][2], acc[mi][ni][3]);
        }
    }
}

// ============================================================================
// Pair phase: thread-per-pair, d^2 = n[r] + n[c] - 2*G[r][c]; fused finalize.
// ============================================================================
__device__ __forceinline__ float softplus_fast(float z) {
    // max(z,0) + log1p(exp(-|z|)); exact in the saturated regime
    return fmaxf(z, 0.0f) + __logf(1.0f + __expf(-fabsf(z)));
}

__global__ void __launch_bounds__(256)
pair_kernel(const float* __restrict__ bias,
            const int*   __restrict__ pos_idx,
            const int*   __restrict__ neg_idx,
            float*       __restrict__ out,
            int P, float invP)
{
    const int tid    = blockIdx.x * blockDim.x + threadIdx.x;
    const int stride = gridDim.x * blockDim.x;
    const float b    = bias[0];
    const int total  = 2 * P;

    float ap = 0.0f, an = 0.0f;
    for (int t = tid; t < total; t += stride) {
        const bool isp = (t < P);
        const int  p   = isp ? t : (t - P);
        const int2 ij  = ((const int2*)(isp ? pos_idx : neg_idx))[p];
        const int  r   = max(ij.x, ij.y);
        const int  c   = min(ij.x, ij.y);
        const float g  = __ldg(&g_G[(size_t)r * NROWS + c]);
        const float d  = g_norm[r] + g_norm[c] - 2.0f * g;
        const float z  = isp ? (d - b) : (b - d);
        const float sp = softplus_fast(z);
        if (isp) ap += sp; else an += sp;
    }

    // warp reduce
    #pragma unroll
    for (int off = 16; off > 0; off >>= 1) {
        ap += __shfl_xor_sync(0xFFFFFFFFu, ap, off);
        an += __shfl_xor_sync(0xFFFFFFFFu, an, off);
    }

    __shared__ float s_p[8], s_n[8];
    const int warp = threadIdx.x >> 5;
    const int lane = threadIdx.x & 31;
    if (lane == 0) { s_p[warp] = ap; s_n[warp] = an; }
    __syncthreads();

    if (threadIdx.x == 0) {
        float tp = 0.0f, tn = 0.0f;
        #pragma unroll
        for (int w = 0; w < 8; ++w) { tp += s_p[w]; tn += s_n[w]; }
        atomicAdd(&g_acc[0], tp);
        atomicAdd(&g_acc[1], tn);
        __threadfence();
        const unsigned ticket = atomicAdd(&g_done, 1u);
        if (ticket == gridDim.x - 1) {   // last block: finalize
            out[0] = g_acc[0] * invP;
            out[1] = g_acc[1] * invP;
        }
    }
}

// ============================================================================
extern "C" void kernel_launch(void* const* d_in, const int* in_sizes, int n_in,
                              void* d_out, int out_size)
{
    const float* X       = (const float*)d_in[0];   // [4096, 256] fp32
    const float* bias    = (const float*)d_in[1];   // [1]
    const int*   pos_idx = (const int*)d_in[2];     // [P, 2]
    const int*   neg_idx = (const int*)d_in[3];     // [P, 2]
    float*       out     = (float*)d_out;           // [2]

    const int P = in_sizes[2] / 2;

    prep_kernel<<<NROWS / 8, 256>>>(X);

    dim3 grid(NROWS / 128, NROWS / 128);            // 32 x 32, upper blocks exit
    gram_kernel<<<grid, 256>>>();

    pair_kernel<<<512, 256>>>(bias, pos_idx, neg_idx, out, P, 1.0f / (float)P);
}

// round 6
// speedup vs baseline: 2.1067x; 1.0865x over previous
#include <cuda_runtime.h>
#include <cuda_fp16.h>
#include <math.h>

#define DIM 256
#define NROWS 4096

// ---- static device scratch (no allocations allowed) ----
__device__ float        g_acc[2];
__device__ unsigned int g_done;
__device__ __half       g_Xh[NROWS * DIM];                    // 2 MB fp16 table
__device__ float        g_norm[NROWS];                        // row squared norms
__device__ float        g_G[(size_t)NROWS * NROWS];           // 64 MB Gram (lower-tri blocks valid)

// ============================================================================
// Prep: fp32 -> fp16 convert, row norms (from the fp16 values, for consistency
// with the Gram MMA), zero accumulators. One warp per row.
// ============================================================================
__global__ void __launch_bounds__(256)
prep_kernel(const float* __restrict__ X)
{
    const int warp = threadIdx.x >> 5;
    const int lane = threadIdx.x & 31;
    const int row  = blockIdx.x * 8 + warp;

    const float4* src = (const float4*)(X + (size_t)row * DIM);
    float4 v0 = src[lane * 2];
    float4 v1 = src[lane * 2 + 1];

    __half2 h0 = __floats2half2_rn(v0.x, v0.y);
    __half2 h1 = __floats2half2_rn(v0.z, v0.w);
    __half2 h2 = __floats2half2_rn(v1.x, v1.y);
    __half2 h3 = __floats2half2_rn(v1.z, v1.w);

    uint4 packed;
    packed.x = *(unsigned int*)&h0;
    packed.y = *(unsigned int*)&h1;
    packed.z = *(unsigned int*)&h2;
    packed.w = *(unsigned int*)&h3;
    ((uint4*)(g_Xh + (size_t)row * DIM))[lane] = packed;

    float2 f0 = __half22float2(h0), f1 = __half22float2(h1);
    float2 f2 = __half22float2(h2), f3 = __half22float2(h3);
    float s = f0.x * f0.x;
    s = fmaf(f0.y, f0.y, s);
    s = fmaf(f1.x, f1.x, s); s = fmaf(f1.y, f1.y, s);
    s = fmaf(f2.x, f2.x, s); s = fmaf(f2.y, f2.y, s);
    s = fmaf(f3.x, f3.x, s); s = fmaf(f3.y, f3.y, s);
    #pragma unroll
    for (int off = 16; off > 0; off >>= 1)
        s += __shfl_xor_sync(0xFFFFFFFFu, s, off);
    if (lane == 0) g_norm[row] = s;

    if (blockIdx.x == 0 && threadIdx.x < 3) {
        if (threadIdx.x < 2) g_acc[threadIdx.x] = 0.0f;
        else                 g_done = 0u;
    }
}

// ============================================================================
// Gram GEMM: G = Xh * Xh^T, fp16 in / fp32 acc, mma.sync.m16n8k16 + ldmatrix.
// Exact lower-triangle launch: 528 blocks, bid -> (bm >= bn).
// Block tile 128x128, 8 warps of 64x32, K chunked by 64 in padded SMEM.
// ============================================================================
__device__ __forceinline__ void mma16816(float c[4],
                                         const unsigned a[4],
                                         const unsigned b[2])
{
    asm volatile(
        "mma.sync.aligned.m16n8k16.row.col.f32.f16.f16.f32 "
        "{%0,%1,%2,%3}, {%4,%5,%6,%7}, {%8,%9}, {%0,%1,%2,%3};\n"
        : "+f"(c[0]), "+f"(c[1]), "+f"(c[2]), "+f"(c[3])
        : "r"(a[0]), "r"(a[1]), "r"(a[2]), "r"(a[3]),
          "r"(b[0]), "r"(b[1]));
}

__device__ __forceinline__ void ldsm_x4(unsigned r[4], const void* p) {
    unsigned addr = (unsigned)__cvta_generic_to_shared(p);
    asm volatile("ldmatrix.sync.aligned.m8n8.x4.shared.b16 {%0,%1,%2,%3}, [%4];"
                 : "=r"(r[0]), "=r"(r[1]), "=r"(r[2]), "=r"(r[3]) : "r"(addr));
}

__device__ __forceinline__ void ldsm_x4_trans(unsigned r[4], const void* p) {
    unsigned addr = (unsigned)__cvta_generic_to_shared(p);
    asm volatile("ldmatrix.sync.aligned.m8n8.x4.trans.shared.b16 {%0,%1,%2,%3}, [%4];"
                 : "=r"(r[0]), "=r"(r[1]), "=r"(r[2]), "=r"(r[3]) : "r"(addr));
}

__global__ void __launch_bounds__(256, 2)
gram_kernel()
{
    // linear bid -> lower-triangle (bm, bn), bm >= bn
    const int bid = blockIdx.x;
    int bm = (int)((sqrtf(8.0f * (float)bid + 1.0f) - 1.0f) * 0.5f);
    while ((bm + 1) * (bm + 2) / 2 <= bid) ++bm;
    while (bm * (bm + 1) / 2 > bid)        --bm;
    const int bn = bid - bm * (bm + 1) / 2;

    __shared__ __half As[128][72];   // +16B row pad: conflict-free LDSM phases
    __shared__ __half Bs[128][72];

    const int tid  = threadIdx.x;
    const int warp = tid >> 5;
    const int lane = tid & 31;
    const int wm   = warp >> 2;      // 0..1  (64-row slabs)
    const int wn   = warp & 3;       // 0..3  (32-col slabs)
    const int tg   = lane >> 2;      // 0..7
    const int tq   = lane & 3;       // 0..3

    float acc[4][4][4];
    #pragma unroll
    for (int mi = 0; mi < 4; ++mi)
        #pragma unroll
        for (int ni = 0; ni < 4; ++ni)
            #pragma unroll
            for (int k = 0; k < 4; ++k) acc[mi][ni][k] = 0.0f;

    const int lr = tid >> 3;          // 0..31
    const int lc = (tid & 7) * 8;     // 0,8,...,56 halves

    // LDSM source coordinates (within the warp's slab)
    const int a_row_off = lane & 15;            // row within 16-row A tile
    const int a_col_off = (lane >> 4) * 8;      // k-half selector
    const int b_row_off = ((lane >> 4) << 3) + (lane & 7);  // row within 16-col B pair
    const int b_col_off = ((lane >> 3) & 1) * 8;

    for (int kc = 0; kc < 4; ++kc) {
        const int kbase = kc * 64;
        #pragma unroll
        for (int rr = 0; rr < 4; ++rr) {
            const int row = rr * 32 + lr;
            uint4 va = *(const uint4*)(g_Xh + (size_t)(bm * 128 + row) * DIM + kbase + lc);
            *(uint4*)(&As[row][lc]) = va;
            uint4 vb = *(const uint4*)(g_Xh + (size_t)(bn * 128 + row) * DIM + kbase + lc);
            *(uint4*)(&Bs[row][lc]) = vb;
        }
        __syncthreads();

        #pragma unroll
        for (int ks = 0; ks < 4; ++ks) {
            const int kk = ks * 16;
            unsigned a[4][4], b[4][2];
            #pragma unroll
            for (int mi = 0; mi < 4; ++mi) {
                ldsm_x4(a[mi], &As[wm * 64 + mi * 16 + a_row_off][kk + a_col_off]);
            }
            #pragma unroll
            for (int p = 0; p < 2; ++p) {
                unsigned br[4];
                ldsm_x4_trans(br, &Bs[wn * 32 + p * 16 + b_row_off][kk + b_col_off]);
                b[2 * p][0]     = br[0];
                b[2 * p][1]     = br[1];
                b[2 * p + 1][0] = br[2];
                b[2 * p + 1][1] = br[3];
            }
            #pragma unroll
            for (int mi = 0; mi < 4; ++mi)
                #pragma unroll
                for (int ni = 0; ni < 4; ++ni)
                    mma16816(acc[mi][ni], a[mi], b[ni]);
        }
        __syncthreads();
    }

    #pragma unroll
    for (int mi = 0; mi < 4; ++mi) {
        const int r0 = bm * 128 + wm * 64 + mi * 16 + tg;
        #pragma unroll
        for (int ni = 0; ni < 4; ++ni) {
            const int c0 = bn * 128 + wn * 32 + ni * 8 + tq * 2;
            *(float2*)(&g_G[(size_t)r0 * NROWS + c0]) =
                make_float2(acc[mi][ni][0], acc[mi][ni][1]);
            *(float2*)(&g_G[(size_t)(r0 + 8) * NROWS + c0]) =
                make_float2(acc[mi][ni][2], acc[mi][ni][3]);
        }
    }
}

// ============================================================================
// Pair phase: thread-per-pair, d^2 = n[r] + n[c] - 2*G[r][c]; fused finalize.
// ============================================================================
__device__ __forceinline__ float softplus_fast(float z) {
    return fmaxf(z, 0.0f) + __logf(1.0f + __expf(-fabsf(z)));
}

__global__ void __launch_bounds__(256)
pair_kernel(const float* __restrict__ bias,
            const int*   __restrict__ pos_idx,
            const int*   __restrict__ neg_idx,
            float*       __restrict__ out,
            int P, float invP)
{
    const int tid    = blockIdx.x * blockDim.x + threadIdx.x;
    const int stride = gridDim.x * blockDim.x;
    const float b    = bias[0];
    const int total  = 2 * P;

    float ap = 0.0f, an = 0.0f;
    for (int t = tid; t < total; t += stride) {
        const bool isp = (t < P);
        const int  p   = isp ? t : (t - P);
        const int2 ij  = ((const int2*)(isp ? pos_idx : neg_idx))[p];
        const int  r   = max(ij.x, ij.y);
        const int  c   = min(ij.x, ij.y);
        const float g  = __ldg(&g_G[(size_t)r * NROWS + c]);
        const float d  = g_norm[r] + g_norm[c] - 2.0f * g;
        const float z  = isp ? (d - b) : (b - d);
        const float sp = softplus_fast(z);
        if (isp) ap += sp; else an += sp;
    }

    #pragma unroll
    for (int off = 16; off > 0; off >>= 1) {
        ap += __shfl_xor_sync(0xFFFFFFFFu, ap, off);
        an += __shfl_xor_sync(0xFFFFFFFFu, an, off);
    }

    __shared__ float s_p[8], s_n[8];
    const int warp = threadIdx.x >> 5;
    const int lane = threadIdx.x & 31;
    if (lane == 0) { s_p[warp] = ap; s_n[warp] = an; }
    __syncthreads();

    if (threadIdx.x == 0) {
        float tp = 0.0f, tn = 0.0f;
        #pragma unroll
        for (int w = 0; w < 8; ++w) { tp += s_p[w]; tn += s_n[w]; }
        atomicAdd(&g_acc[0], tp);
        atomicAdd(&g_acc[1], tn);
        __threadfence();
        const unsigned ticket = atomicAdd(&g_done, 1u);
        if (ticket == gridDim.x - 1) {
            out[0] = g_acc[0] * invP;
            out[1] = g_acc[1] * invP;
        }
    }
}

// ============================================================================
extern "C" void kernel_launch(void* const* d_in, const int* in_sizes, int n_in,
                              void* d_out, int out_size)
{
    const float* X       = (const float*)d_in[0];   // [4096, 256] fp32
    const float* bias    = (const float*)d_in[1];   // [1]
    const int*   pos_idx = (const int*)d_in[2];     // [P, 2]
    const int*   neg_idx = (const int*)d_in[3];     // [P, 2]
    float*       out     = (float*)d_out;           // [2]

    const int P = in_sizes[2] / 2;

    prep_kernel<<<NROWS / 8, 256>>>(X);

    const int nblk = 32 * 33 / 2;                   // 528 lower-tri blocks
    gram_kernel<<<nblk, 256>>>();

    pair_kernel<<<512, 256>>>(bias, pos_idx, neg_idx, out, P, 1.0f / (float)P);
}